// round 16
// baseline (speedup 1.0000x reference)
#include <cuda_runtime.h>
#include <cuda_fp16.h>
#include <cstdint>

// Problem constants (Qwen3MoeSparseMoeBlock_2413771621126)
#define T_TOK   1024
#define HID     2048
#define NEXP    16
#define TOPK    4
#define INTER   768
#define INTER2  1536

// conv_gup progress: blocks per expert (each block converts 512 float4)
#define GU_CONV_BLOCKS_PER_E 1536

// ---------------- device scratch (static; allocation-free) ----------------
__device__ int   g_cnt[NEXP];
__device__ int   g_done[NEXP];
__device__ int   g_tok[NEXP * T_TOK];
__device__ float g_wt [NEXP * T_TOK];

__device__ __align__(128) __half g_xh[(size_t)T_TOK * HID];
__device__ __align__(128) __half g_gh[(size_t)NEXP * HID * INTER2];
__device__ __align__(128) __half g_dh[(size_t)NEXP * INTER * HID];
__device__ __align__(128) __half g_hf[(size_t)NEXP * T_TOK * INTER];

// ---------------- helpers ----------------
__device__ __forceinline__ uint32_t smem_u32(const void* p) {
    uint32_t a;
    asm("{ .reg .u64 t; cvta.to.shared.u64 t, %1; cvt.u32.u64 %0, t; }" : "=r"(a) : "l"(p));
    return a;
}

// fp16 convert of float4 -> 4 fp16 (uint2)
__device__ __forceinline__ uint2 conv4h(float4 f) {
    uint2 r;
    r.x = ((uint32_t)__half_as_ushort(__float2half(f.y)) << 16) | __half_as_ushort(__float2half(f.x));
    r.y = ((uint32_t)__half_as_ushort(__float2half(f.w)) << 16) | __half_as_ushort(__float2half(f.z));
    return r;
}

#define MMA_F16(d, a, b) \
    asm volatile("mma.sync.aligned.m16n8k16.row.col.f32.f16.f16.f32 " \
        "{%0,%1,%2,%3}, {%4,%5,%6,%7}, {%8,%9}, {%0,%1,%2,%3};" \
        : "+f"((d)[0]), "+f"((d)[1]), "+f"((d)[2]), "+f"((d)[3]) \
        : "r"((a)[0]), "r"((a)[1]), "r"((a)[2]), "r"((a)[3]), \
          "r"((b)[0]), "r"((b)[1]))

#define LDSM4(r, a) \
    asm volatile("ldmatrix.sync.aligned.m8n8.x4.shared.b16 {%0,%1,%2,%3}, [%4];" \
        : "=r"((r)[0]), "=r"((r)[1]), "=r"((r)[2]), "=r"((r)[3]) : "r"(a))
#define LDSM4T(r, a) \
    asm volatile("ldmatrix.sync.aligned.m8n8.x4.trans.shared.b16 {%0,%1,%2,%3}, [%4];" \
        : "=r"((r)[0]), "=r"((r)[1]), "=r"((r)[2]), "=r"((r)[3]) : "r"(a))

#define CP16(dst, src) \
    asm volatile("cp.async.cg.shared.global [%0], [%1], 16;" \
        :: "r"(dst), "l"(__cvta_generic_to_global(src)))
#define CP_COMMIT() asm volatile("cp.async.commit_group;" ::: "memory")
#define CP_WAIT1()  asm volatile("cp.async.wait_group 1;" ::: "memory")

// ---------------- counters (must precede the convert on the timeline) -----
__global__ void zcnt_kernel() {
    if (threadIdx.x < NEXP) {
        g_cnt[threadIdx.x]  = 0;
        g_done[threadIdx.x] = 0;
    }
}

// ---------------- phase 0: zero output ----------------
__global__ void zero_kernel(float* __restrict__ out, int n) {
    int i = blockIdx.x * blockDim.x + threadIdx.x;
    if (i < n) out[i] = 0.0f;
}

// ---------------- gup convert with per-expert progress signal -------------
// 2 float4/thread; 512 float4 per block; exactly GU_CONV_BLOCKS_PER_E blocks/expert.
__global__ void __launch_bounds__(256) convgu_kernel(
    const float4* __restrict__ src, uint2* __restrict__ dst)
{
    int i = (blockIdx.x * blockDim.x + threadIdx.x) * 2;
    float4 f0 = src[i], f1 = src[i + 1];
    dst[i]     = conv4h(f0);
    dst[i + 1] = conv4h(f1);
    __threadfence();
    __syncthreads();
    if (threadIdx.x == 0)
        atomicAdd(&g_done[blockIdx.x / GU_CONV_BLOCKS_PER_E], 1);
}

// ---------------- dw convert (plain, 2 float4/thread) ----------------
__global__ void __launch_bounds__(256) convh_kernel(
    const float4* __restrict__ src, uint2* __restrict__ dst, int n4)
{
    int i = (blockIdx.x * blockDim.x + threadIdx.x) * 2;
    if (i + 1 < n4) {
        float4 f0 = src[i], f1 = src[i + 1];
        dst[i]     = conv4h(f0);
        dst[i + 1] = conv4h(f1);
    } else if (i < n4) {
        dst[i] = conv4h(src[i]);
    }
}

// ---------------- phase 1: router (+ fused x fp16 convert) ----------------
__global__ void __launch_bounds__(128) router_kernel(
    const float* __restrict__ x, const float* __restrict__ rw,
    __half* __restrict__ xh)
{
    __shared__ float4 rw_s[NEXP][130];

    int tid  = threadIdx.x;
    int lane = tid & 31;
    int w    = tid >> 5;
    int t    = blockIdx.x * 4 + w;

    float acc[NEXP];
#pragma unroll
    for (int e = 0; e < NEXP; e++) acc[e] = 0.0f;

#pragma unroll 1
    for (int c = 0; c < HID / 512; c++) {
        __syncthreads();
        for (int i = tid; i < NEXP * 128; i += 128) {
            int e = i >> 7, k4 = i & 127;
            rw_s[e][k4] = reinterpret_cast<const float4*>(rw + e * HID + c * 512)[k4];
        }
        __syncthreads();

        const float4* xp = reinterpret_cast<const float4*>(x + (size_t)t * HID + c * 512);
#pragma unroll
        for (int i = 0; i < 4; i++) {
            int k4 = lane + i * 32;
            float4 xv = xp[k4];
            *reinterpret_cast<uint2*>(xh + (size_t)t * HID + c * 512 + k4 * 4) = conv4h(xv);
#pragma unroll
            for (int e = 0; e < NEXP; e++) {
                float4 rv = rw_s[e][k4];
                acc[e] += xv.x * rv.x + xv.y * rv.y + xv.z * rv.z + xv.w * rv.w;
            }
        }
    }

#pragma unroll
    for (int e = 0; e < NEXP; e++) {
#pragma unroll
        for (int off = 16; off > 0; off >>= 1)
            acc[e] += __shfl_down_sync(0xFFFFFFFFu, acc[e], off);
    }

    if (lane == 0) {
        int idx[TOPK]; float val[TOPK]; bool used[NEXP];
#pragma unroll
        for (int e = 0; e < NEXP; e++) used[e] = false;
#pragma unroll
        for (int k = 0; k < TOPK; k++) {
            float best = -1e30f; int bi = 0;
            for (int e = 0; e < NEXP; e++)
                if (!used[e] && acc[e] > best) { best = acc[e]; bi = e; }
            used[bi] = true; idx[k] = bi; val[k] = best;
        }
        float mx = val[0], s = 0.0f, ev[TOPK];
#pragma unroll
        for (int k = 0; k < TOPK; k++) { ev[k] = expf(val[k] - mx); s += ev[k]; }
        float inv = 1.0f / s;
#pragma unroll
        for (int k = 0; k < TOPK; k++) {
            int e = idx[k];
            int pos = atomicAdd(&g_cnt[e], 1);
            g_tok[e * T_TOK + pos] = t;
            g_wt [e * T_TOK + pos] = ev[k] * inv;
        }
    }
}

// ============================================================
// smem (per stage, bytes), 3-stage cp.async ring, K-stage = 64:
//  A: 128 rows x 64 fp16, pitch 144B -> 18432 @ 0
//  gate_up B: 64k x 128n fp16, pitch 272B -> 17408 @ 18432 ; stage 35840
//  down    B: 64k x 128n fp16, pitch 272B -> 17408 @ 18432 ; stage 35840
// ============================================================
#define GU_STAGE 35840
#define GU_META  (3 * GU_STAGE)
#define GU_SMEM  (GU_META + 1024)
#define DN_STAGE 35840
#define DN_META  (3 * DN_STAGE)
#define DN_SMEM  (DN_META + 1024)

// ---------------- phase 2: gate_up GEMM (spin-waits on conv progress) -----
__device__ __forceinline__ void gu_load(
    int e, int nbase, int k0, uint32_t sb, const int* stok, int tid)
{
#pragma unroll
    for (int i = 0; i < 4; i++) {
        int c = tid + i * 256;
        int row = c >> 3, seg = c & 7;
        int tok = stok[row];
        CP16(sb + row * 144 + seg * 16, g_xh + (size_t)tok * HID + k0 + seg * 8);
    }
#pragma unroll
    for (int i = 0; i < 4; i++) {
        int c = tid + i * 256;
        int k = c >> 4, seg = c & 15;
        int n = seg * 8;
        int col = (n < 64) ? (nbase + n) : (INTER + nbase + (n - 64));
        CP16(sb + 18432 + k * 272 + seg * 16,
             g_gh + ((size_t)e * HID + k0 + k) * INTER2 + col);
    }
}

__global__ void __launch_bounds__(256, 2) gateup_mma(int dummy)
{
    extern __shared__ char smem[];
    int e = blockIdx.z;
    int cnt = g_cnt[e];
    int mbase = blockIdx.x * 128;
    if (mbase >= cnt) return;
    int nbase = blockIdx.y * 64;

    int tid = threadIdx.x;
    int lane = tid & 31, wid = tid >> 5;
    int wm = (wid & 3) * 32;
    int wn = (wid >> 2) * 32;

    // wait until this expert's gup weights are converted
    if (tid == 0) {
        volatile int* dp = (volatile int*)&g_done[e];
        while (*dp < GU_CONV_BLOCKS_PER_E)
            asm volatile("nanosleep.u32 256;");
    }
    __syncthreads();
    __threadfence();

    uint32_t sbase = smem_u32(smem);
    int*   stok = (int*)  (smem + GU_META);
    float* swt  = (float*)(smem + GU_META + 512);
    if (tid < 128) {
        int gm = mbase + tid;
        stok[tid] = (gm < cnt) ? g_tok[e * T_TOK + gm] : 0;
        swt[tid]  = (gm < cnt) ? g_wt [e * T_TOK + gm] : 0.0f;
    }
    __syncthreads();

    float accG[2][4][4], accU[2][4][4];
#pragma unroll
    for (int i = 0; i < 2; i++)
#pragma unroll
        for (int j = 0; j < 4; j++)
#pragma unroll
            for (int c = 0; c < 4; c++) { accG[i][j][c] = 0.0f; accU[i][j][c] = 0.0f; }

    const int S = HID / 64;   // 32
    gu_load(e, nbase, 0,  sbase,            stok, tid); CP_COMMIT();
    gu_load(e, nbase, 64, sbase + GU_STAGE, stok, tid); CP_COMMIT();

    int bc = 0, bl = 2;
#pragma unroll 1
    for (int s = 0; s < S; s++) {
        CP_WAIT1();
        __syncthreads();
        if (s + 2 < S)
            gu_load(e, nbase, (s + 2) * 64, sbase + bl * GU_STAGE, stok, tid);
        CP_COMMIT();

        uint32_t st = sbase + bc * GU_STAGE;
#pragma unroll
        for (int ks = 0; ks < 4; ks++) {
            uint32_t a[2][4];
#pragma unroll
            for (int mt = 0; mt < 2; mt++) {
                uint32_t aa = st + (wm + mt * 16 + (lane & 15)) * 144
                            + (ks * 16 + (lane >> 4) * 8) * 2;
                LDSM4(a[mt], aa);
            }
#pragma unroll
            for (int ng = 0; ng < 2; ng++) {
                uint32_t ba = st + 18432 + (ks * 16 + (lane & 15)) * 272
                            + (wn + ng * 16 + (lane >> 4) * 8) * 2;
                uint32_t bg[4], bu[4];
                LDSM4T(bg, ba);
                LDSM4T(bu, ba + 128);
#pragma unroll
                for (int half = 0; half < 2; half++) {
                    int j = ng * 2 + half;
#pragma unroll
                    for (int mt = 0; mt < 2; mt++) {
                        MMA_F16(accG[mt][j], a[mt], &bg[half * 2]);
                        MMA_F16(accU[mt][j], a[mt], &bu[half * 2]);
                    }
                }
            }
        }
        bc = (bc == 2) ? 0 : bc + 1;
        bl = (bl == 2) ? 0 : bl + 1;
    }

#pragma unroll
    for (int mt = 0; mt < 2; mt++) {
#pragma unroll
        for (int j = 0; j < 4; j++) {
            int col = wn + (j >> 1) * 16 + (j & 1) * 8 + (lane & 3) * 2;
#pragma unroll
            for (int rh = 0; rh < 2; rh++) {
                int m = wm + mt * 16 + (lane >> 2) + rh * 8;
                int gm = mbase + m;
                if (gm >= cnt) continue;
                float w = swt[m];
                float g0 = accG[mt][j][rh * 2 + 0], u0 = accU[mt][j][rh * 2 + 0];
                float g1 = accG[mt][j][rh * 2 + 1], u1 = accU[mt][j][rh * 2 + 1];
                float h0 = (g0 / (1.0f + expf(-g0))) * u0 * w;
                float h1 = (g1 / (1.0f + expf(-g1))) * u1 * w;
                uint32_t pk = ((uint32_t)__half_as_ushort(__float2half(h1)) << 16)
                            |  (uint32_t)__half_as_ushort(__float2half(h0));
                size_t off = ((size_t)e * T_TOK + gm) * INTER + nbase + col;
                *reinterpret_cast<uint32_t*>(g_hf + off) = pk;
            }
        }
    }
}

// ---------------- phase 3: down GEMM (N-tile 128) + atomic scatter --------
__device__ __forceinline__ void dn_load(
    int e, int mbase, int nbase, int k0, uint32_t sb, int tid)
{
#pragma unroll
    for (int i = 0; i < 4; i++) {
        int c = tid + i * 256;
        int row = c >> 3, seg = c & 7;
        CP16(sb + row * 144 + seg * 16,
             g_hf + ((size_t)e * T_TOK + mbase + row) * INTER + k0 + seg * 8);
    }
#pragma unroll
    for (int i = 0; i < 4; i++) {
        int c = tid + i * 256;
        int k = c >> 4, seg = c & 15;
        CP16(sb + 18432 + k * 272 + seg * 16,
             g_dh + ((size_t)e * INTER + k0 + k) * HID + nbase + seg * 8);
    }
}

__global__ void __launch_bounds__(256, 2) down_mma(float* __restrict__ out)
{
    extern __shared__ char smem[];
    int e = blockIdx.z;
    int cnt = g_cnt[e];
    int mbase = blockIdx.x * 128;
    if (mbase >= cnt) return;
    int nbase = blockIdx.y * 128;

    int tid = threadIdx.x;
    int lane = tid & 31, wid = tid >> 5;
    int wm = (wid & 3) * 32;
    int wn = (wid >> 2) * 64;

    uint32_t sbase = smem_u32(smem);
    int* stok = (int*)(smem + DN_META);
    if (tid < 128) {
        int gm = mbase + tid;
        stok[tid] = (gm < cnt) ? g_tok[e * T_TOK + gm] : -1;
    }
    __syncthreads();

    float acc[2][8][4];
#pragma unroll
    for (int i = 0; i < 2; i++)
#pragma unroll
        for (int j = 0; j < 8; j++)
#pragma unroll
            for (int c = 0; c < 4; c++) acc[i][j][c] = 0.0f;

    const int S = INTER / 64;  // 12
    dn_load(e, mbase, nbase, 0,  sbase,            tid); CP_COMMIT();
    dn_load(e, mbase, nbase, 64, sbase + DN_STAGE, tid); CP_COMMIT();

    int bc = 0, bl = 2;
#pragma unroll 1
    for (int s = 0; s < S; s++) {
        CP_WAIT1();
        __syncthreads();
        if (s + 2 < S)
            dn_load(e, mbase, nbase, (s + 2) * 64, sbase + bl * DN_STAGE, tid);
        CP_COMMIT();

        uint32_t st = sbase + bc * DN_STAGE;
#pragma unroll
        for (int ks = 0; ks < 4; ks++) {
            uint32_t a[2][4];
#pragma unroll
            for (int mt = 0; mt < 2; mt++) {
                uint32_t aa = st + (wm + mt * 16 + (lane & 15)) * 144
                            + (ks * 16 + (lane >> 4) * 8) * 2;
                LDSM4(a[mt], aa);
            }
#pragma unroll
            for (int ng = 0; ng < 4; ng++) {
                uint32_t ba = st + 18432 + (ks * 16 + (lane & 15)) * 272
                            + (wn + ng * 16 + (lane >> 4) * 8) * 2;
                uint32_t bh[4];
                LDSM4T(bh, ba);
#pragma unroll
                for (int half = 0; half < 2; half++) {
                    int j = ng * 2 + half;
#pragma unroll
                    for (int mt = 0; mt < 2; mt++)
                        MMA_F16(acc[mt][j], a[mt], &bh[half * 2]);
                }
            }
        }
        bc = (bc == 2) ? 0 : bc + 1;
        bl = (bl == 2) ? 0 : bl + 1;
    }

#pragma unroll
    for (int mt = 0; mt < 2; mt++) {
#pragma unroll
        for (int rh = 0; rh < 2; rh++) {
            int m = wm + mt * 16 + (lane >> 2) + rh * 8;
            int tok = stok[m];
            if (tok < 0) continue;
            float* op = &out[(size_t)tok * HID + nbase];
#pragma unroll
            for (int j = 0; j < 8; j++) {
                int col = wn + (j >> 1) * 16 + (j & 1) * 8 + (lane & 3) * 2;
                atomicAdd(op + col,     acc[mt][j][rh * 2 + 0]);
                atomicAdd(op + col + 1, acc[mt][j][rh * 2 + 1]);
            }
        }
    }
}

// ---------------- launch ----------------
extern "C" void kernel_launch(void* const* d_in, const int* in_sizes, int n_in,
                              void* d_out, int out_size)
{
    const float* x    = (const float*)d_in[0];
    const float* rw   = (const float*)d_in[1];
    const float* gup  = (const float*)d_in[2];
    const float* dw   = (const float*)d_in[3];
    float* out = (float*)d_out;

    static cudaStream_t s2 = nullptr;
    static cudaEvent_t  ev_fork = nullptr, ev_dw = nullptr;
    static bool init_done = false;
    if (!init_done) {
        cudaFuncSetAttribute(gateup_mma, cudaFuncAttributeMaxDynamicSharedMemorySize, GU_SMEM);
        cudaFuncSetAttribute(down_mma,   cudaFuncAttributeMaxDynamicSharedMemorySize, DN_SMEM);
        cudaStreamCreateWithFlags(&s2, cudaStreamNonBlocking);
        cudaEventCreateWithFlags(&ev_fork, cudaEventDisableTiming);
        cudaEventCreateWithFlags(&ev_dw,   cudaEventDisableTiming);
        init_done = true;
    }

    __half *xh, *gh, *dh;
    cudaGetSymbolAddress((void**)&xh, g_xh);
    cudaGetSymbolAddress((void**)&gh, g_gh);
    cudaGetSymbolAddress((void**)&dh, g_dh);

    cudaStream_t s1 = 0;

    // counters first (g_done must be 0 before conv starts incrementing)
    zcnt_kernel<<<1, 32, 0, s1>>>();
    cudaEventRecord(ev_fork, s1);
    cudaStreamWaitEvent(s2, ev_fork, 0);

    // s2: whole gup convert with progress signal, then dw convert
    convgu_kernel<<<NEXP * GU_CONV_BLOCKS_PER_E, 256, 0, s2>>>(
        (const float4*)gup, (uint2*)gh);
    int n4d = NEXP * INTER * HID / 4;
    convh_kernel<<<(n4d / 2 + 255) / 256, 256, 0, s2>>>(
        (const float4*)dw, (uint2*)dh, n4d);
    cudaEventRecord(ev_dw, s2);

    // s1: zero out + router (produces fp16 x)
    int n_out = T_TOK * HID;
    zero_kernel<<<(n_out + 511) / 512, 512, 0, s1>>>(out, n_out);
    router_kernel<<<T_TOK / 4, 128, 0, s1>>>(x, rw, xh);

    // gateup: no event dependency — spin-waits per expert on g_done
    dim3 gridG(T_TOK / 128, INTER / 64, NEXP);   // (8, 12, 16)
    gateup_mma<<<gridG, 256, GU_SMEM, s1>>>(0);

    // down: after gateup (s1 order) + dw convert
    cudaStreamWaitEvent(s1, ev_dw, 0);
    dim3 gridD(T_TOK / 128, HID / 128, NEXP);    // (8, 16, 16)
    down_mma<<<gridD, 256, DN_SMEM, s1>>>(out);
}

// round 17
// speedup vs baseline: 1.1614x; 1.1614x over previous
#include <cuda_runtime.h>
#include <cuda_fp16.h>
#include <cstdint>

// Problem constants (Qwen3MoeSparseMoeBlock_2413771621126)
#define T_TOK   1024
#define HID     2048
#define NEXP    16
#define TOPK    4
#define INTER   768
#define INTER2  1536

// ---------------- device scratch (static; allocation-free) ----------------
__device__ int   g_cnt[NEXP];
__device__ int   g_tok[NEXP * T_TOK];
__device__ float g_wt [NEXP * T_TOK];

__device__ __align__(128) __half g_xh[(size_t)T_TOK * HID];
__device__ __align__(128) __half g_gh[(size_t)NEXP * HID * INTER2];
__device__ __align__(128) __half g_dh[(size_t)NEXP * INTER * HID];
__device__ __align__(128) __half g_hf[(size_t)NEXP * T_TOK * INTER];

// ---------------- helpers ----------------
__device__ __forceinline__ uint32_t smem_u32(const void* p) {
    uint32_t a;
    asm("{ .reg .u64 t; cvta.to.shared.u64 t, %1; cvt.u32.u64 %0, t; }" : "=r"(a) : "l"(p));
    return a;
}

// fp16 convert of float4 -> 4 fp16 (uint2)
__device__ __forceinline__ uint2 conv4h(float4 f) {
    uint2 r;
    r.x = ((uint32_t)__half_as_ushort(__float2half(f.y)) << 16) | __half_as_ushort(__float2half(f.x));
    r.y = ((uint32_t)__half_as_ushort(__float2half(f.w)) << 16) | __half_as_ushort(__float2half(f.z));
    return r;
}

#define MMA_F16(d, a, b) \
    asm volatile("mma.sync.aligned.m16n8k16.row.col.f32.f16.f16.f32 " \
        "{%0,%1,%2,%3}, {%4,%5,%6,%7}, {%8,%9}, {%0,%1,%2,%3};" \
        : "+f"((d)[0]), "+f"((d)[1]), "+f"((d)[2]), "+f"((d)[3]) \
        : "r"((a)[0]), "r"((a)[1]), "r"((a)[2]), "r"((a)[3]), \
          "r"((b)[0]), "r"((b)[1]))

#define LDSM4(r, a) \
    asm volatile("ldmatrix.sync.aligned.m8n8.x4.shared.b16 {%0,%1,%2,%3}, [%4];" \
        : "=r"((r)[0]), "=r"((r)[1]), "=r"((r)[2]), "=r"((r)[3]) : "r"(a))
#define LDSM4T(r, a) \
    asm volatile("ldmatrix.sync.aligned.m8n8.x4.trans.shared.b16 {%0,%1,%2,%3}, [%4];" \
        : "=r"((r)[0]), "=r"((r)[1]), "=r"((r)[2]), "=r"((r)[3]) : "r"(a))

#define CP16(dst, src) \
    asm volatile("cp.async.cg.shared.global [%0], [%1], 16;" \
        :: "r"(dst), "l"(__cvta_generic_to_global(src)))
#define CP_COMMIT() asm volatile("cp.async.commit_group;" ::: "memory")
#define CP_WAIT1()  asm volatile("cp.async.wait_group 1;" ::: "memory")

// ---------------- phase 0 ----------------
__global__ void zero_kernel(float* __restrict__ out, int n) {
    int i = blockIdx.x * blockDim.x + threadIdx.x;
    if (i < n) out[i] = 0.0f;
    if (blockIdx.x == 0 && threadIdx.x < NEXP) g_cnt[threadIdx.x] = 0;
}

// ---------------- fp32 -> fp16 convert (weights), 2 float4/thread ----------
__global__ void __launch_bounds__(256) convh_kernel(
    const float4* __restrict__ src, uint2* __restrict__ dst, int n4)
{
    int i = (blockIdx.x * blockDim.x + threadIdx.x) * 2;
    if (i + 1 < n4) {
        float4 f0 = src[i], f1 = src[i + 1];
        dst[i]     = conv4h(f0);
        dst[i + 1] = conv4h(f1);
    } else if (i < n4) {
        dst[i] = conv4h(src[i]);
    }
}

// ---------------- phase 1: router (+ fused x fp16 convert) ----------------
__global__ void __launch_bounds__(128) router_kernel(
    const float* __restrict__ x, const float* __restrict__ rw,
    __half* __restrict__ xh)
{
    __shared__ float4 rw_s[NEXP][130];

    int tid  = threadIdx.x;
    int lane = tid & 31;
    int w    = tid >> 5;
    int t    = blockIdx.x * 4 + w;

    float acc[NEXP];
#pragma unroll
    for (int e = 0; e < NEXP; e++) acc[e] = 0.0f;

#pragma unroll 1
    for (int c = 0; c < HID / 512; c++) {
        __syncthreads();
        for (int i = tid; i < NEXP * 128; i += 128) {
            int e = i >> 7, k4 = i & 127;
            rw_s[e][k4] = reinterpret_cast<const float4*>(rw + e * HID + c * 512)[k4];
        }
        __syncthreads();

        const float4* xp = reinterpret_cast<const float4*>(x + (size_t)t * HID + c * 512);
#pragma unroll
        for (int i = 0; i < 4; i++) {
            int k4 = lane + i * 32;
            float4 xv = xp[k4];
            *reinterpret_cast<uint2*>(xh + (size_t)t * HID + c * 512 + k4 * 4) = conv4h(xv);
#pragma unroll
            for (int e = 0; e < NEXP; e++) {
                float4 rv = rw_s[e][k4];
                acc[e] += xv.x * rv.x + xv.y * rv.y + xv.z * rv.z + xv.w * rv.w;
            }
        }
    }

#pragma unroll
    for (int e = 0; e < NEXP; e++) {
#pragma unroll
        for (int off = 16; off > 0; off >>= 1)
            acc[e] += __shfl_down_sync(0xFFFFFFFFu, acc[e], off);
    }

    if (lane == 0) {
        int idx[TOPK]; float val[TOPK]; bool used[NEXP];
#pragma unroll
        for (int e = 0; e < NEXP; e++) used[e] = false;
#pragma unroll
        for (int k = 0; k < TOPK; k++) {
            float best = -1e30f; int bi = 0;
            for (int e = 0; e < NEXP; e++)
                if (!used[e] && acc[e] > best) { best = acc[e]; bi = e; }
            used[bi] = true; idx[k] = bi; val[k] = best;
        }
        float mx = val[0], s = 0.0f, ev[TOPK];
#pragma unroll
        for (int k = 0; k < TOPK; k++) { ev[k] = expf(val[k] - mx); s += ev[k]; }
        float inv = 1.0f / s;
#pragma unroll
        for (int k = 0; k < TOPK; k++) {
            int e = idx[k];
            int pos = atomicAdd(&g_cnt[e], 1);
            g_tok[e * T_TOK + pos] = t;
            g_wt [e * T_TOK + pos] = ev[k] * inv;
        }
    }
}

// ============================================================
// smem (per stage, bytes), 3-stage cp.async ring, K-stage = 64:
//  gate_up: A 64 rows x 64 fp16, pitch 144B -> 9216 @ 0
//           B 64k x 128n fp16, pitch 272B -> 17408 @ 9216 ; stage 26624
//  down:    A 128 rows x 64 fp16, pitch 144B -> 18432 @ 0
//           B 64k x 128n fp16, pitch 272B -> 17408 @ 18432 ; stage 35840
// ============================================================
#define GU_STAGE 26624
#define GU_META  (3 * GU_STAGE)   // 79872
#define GU_SMEM  (GU_META + 1024) // 80896
#define DN_STAGE 35840
#define DN_META  (3 * DN_STAGE)
#define DN_SMEM  (DN_META + 1024)

// ---------------- phase 2: gate_up GEMM (M-tile 64) ----------------
__device__ __forceinline__ void gu_load(
    int e, int nbase, int k0, uint32_t sb, const int* stok, int tid)
{
    // A: 64 rows x 8 segs = 512 cp16 / 256 thr = 2 each
#pragma unroll
    for (int i = 0; i < 2; i++) {
        int c = tid + i * 256;
        int row = c >> 3, seg = c & 7;
        int tok = stok[row];
        CP16(sb + row * 144 + seg * 16, g_xh + (size_t)tok * HID + k0 + seg * 8);
    }
    // B: 64 k-rows x 16 segs = 1024 cp16 / 256 thr = 4 each
#pragma unroll
    for (int i = 0; i < 4; i++) {
        int c = tid + i * 256;
        int k = c >> 4, seg = c & 15;
        int n = seg * 8;
        int col = (n < 64) ? (nbase + n) : (INTER + nbase + (n - 64));
        CP16(sb + 9216 + k * 272 + seg * 16,
             g_gh + ((size_t)e * HID + k0 + k) * INTER2 + col);
    }
}

__global__ void __launch_bounds__(256, 2) gateup_mma(int dummy)
{
    extern __shared__ char smem[];
    int e = blockIdx.z;
    int cnt = g_cnt[e];
    int mbase = blockIdx.x * 64;
    if (mbase >= cnt) return;
    int nbase = blockIdx.y * 64;

    int tid = threadIdx.x;
    int lane = tid & 31, wid = tid >> 5;
    int wm = (wid & 1) * 32;       // 2 m-groups of 32
    int wn = (wid >> 1) * 16;      // 4 n-groups of 16

    uint32_t sbase = smem_u32(smem);
    int*   stok = (int*)  (smem + GU_META);
    float* swt  = (float*)(smem + GU_META + 512);
    if (tid < 64) {
        int gm = mbase + tid;
        stok[tid] = (gm < cnt) ? g_tok[e * T_TOK + gm] : 0;
        swt[tid]  = (gm < cnt) ? g_wt [e * T_TOK + gm] : 0.0f;
    }
    __syncthreads();

    float accG[2][2][4], accU[2][2][4];
#pragma unroll
    for (int i = 0; i < 2; i++)
#pragma unroll
        for (int j = 0; j < 2; j++)
#pragma unroll
            for (int c = 0; c < 4; c++) { accG[i][j][c] = 0.0f; accU[i][j][c] = 0.0f; }

    const int S = HID / 64;   // 32
    gu_load(e, nbase, 0,  sbase,            stok, tid); CP_COMMIT();
    gu_load(e, nbase, 64, sbase + GU_STAGE, stok, tid); CP_COMMIT();

    int bc = 0, bl = 2;
#pragma unroll 1
    for (int s = 0; s < S; s++) {
        CP_WAIT1();
        __syncthreads();
        if (s + 2 < S)
            gu_load(e, nbase, (s + 2) * 64, sbase + bl * GU_STAGE, stok, tid);
        CP_COMMIT();

        uint32_t st = sbase + bc * GU_STAGE;
#pragma unroll
        for (int ks = 0; ks < 4; ks++) {
            uint32_t a[2][4];
#pragma unroll
            for (int mt = 0; mt < 2; mt++) {
                uint32_t aa = st + (wm + mt * 16 + (lane & 15)) * 144
                            + (ks * 16 + (lane >> 4) * 8) * 2;
                LDSM4(a[mt], aa);
            }
            uint32_t ba = st + 9216 + (ks * 16 + (lane & 15)) * 272
                        + (wn + (lane >> 4) * 8) * 2;
            uint32_t bg[4], bu[4];
            LDSM4T(bg, ba);
            LDSM4T(bu, ba + 128);          // up cols at +64 fp16
#pragma unroll
            for (int half = 0; half < 2; half++) {
#pragma unroll
                for (int mt = 0; mt < 2; mt++) {
                    MMA_F16(accG[mt][half], a[mt], &bg[half * 2]);
                    MMA_F16(accU[mt][half], a[mt], &bu[half * 2]);
                }
            }
        }
        bc = (bc == 2) ? 0 : bc + 1;
        bl = (bl == 2) ? 0 : bl + 1;
    }

    // epilogue: h = silu(gate) * up * wt -> fp16 global
#pragma unroll
    for (int mt = 0; mt < 2; mt++) {
#pragma unroll
        for (int j = 0; j < 2; j++) {
            int col = wn + j * 8 + (lane & 3) * 2;
#pragma unroll
            for (int rh = 0; rh < 2; rh++) {
                int m = wm + mt * 16 + (lane >> 2) + rh * 8;
                int gm = mbase + m;
                if (gm >= cnt) continue;
                float w = swt[m];
                float g0 = accG[mt][j][rh * 2 + 0], u0 = accU[mt][j][rh * 2 + 0];
                float g1 = accG[mt][j][rh * 2 + 1], u1 = accU[mt][j][rh * 2 + 1];
                float h0 = (g0 / (1.0f + expf(-g0))) * u0 * w;
                float h1 = (g1 / (1.0f + expf(-g1))) * u1 * w;
                uint32_t pk = ((uint32_t)__half_as_ushort(__float2half(h1)) << 16)
                            |  (uint32_t)__half_as_ushort(__float2half(h0));
                size_t off = ((size_t)e * T_TOK + gm) * INTER + nbase + col;
                *reinterpret_cast<uint32_t*>(g_hf + off) = pk;
            }
        }
    }
}

// ---------------- phase 3: down GEMM (N-tile 128) + atomic scatter --------
__device__ __forceinline__ void dn_load(
    int e, int mbase, int nbase, int k0, uint32_t sb, int tid)
{
#pragma unroll
    for (int i = 0; i < 4; i++) {
        int c = tid + i * 256;
        int row = c >> 3, seg = c & 7;
        CP16(sb + row * 144 + seg * 16,
             g_hf + ((size_t)e * T_TOK + mbase + row) * INTER + k0 + seg * 8);
    }
#pragma unroll
    for (int i = 0; i < 4; i++) {
        int c = tid + i * 256;
        int k = c >> 4, seg = c & 15;
        CP16(sb + 18432 + k * 272 + seg * 16,
             g_dh + ((size_t)e * INTER + k0 + k) * HID + nbase + seg * 8);
    }
}

__global__ void __launch_bounds__(256, 2) down_mma(float* __restrict__ out)
{
    extern __shared__ char smem[];
    int e = blockIdx.z;
    int cnt = g_cnt[e];
    int mbase = blockIdx.x * 128;
    if (mbase >= cnt) return;
    int nbase = blockIdx.y * 128;

    int tid = threadIdx.x;
    int lane = tid & 31, wid = tid >> 5;
    int wm = (wid & 3) * 32;
    int wn = (wid >> 2) * 64;

    uint32_t sbase = smem_u32(smem);
    int* stok = (int*)(smem + DN_META);
    if (tid < 128) {
        int gm = mbase + tid;
        stok[tid] = (gm < cnt) ? g_tok[e * T_TOK + gm] : -1;
    }
    __syncthreads();

    float acc[2][8][4];
#pragma unroll
    for (int i = 0; i < 2; i++)
#pragma unroll
        for (int j = 0; j < 8; j++)
#pragma unroll
            for (int c = 0; c < 4; c++) acc[i][j][c] = 0.0f;

    const int S = INTER / 64;  // 12
    dn_load(e, mbase, nbase, 0,  sbase,            tid); CP_COMMIT();
    dn_load(e, mbase, nbase, 64, sbase + DN_STAGE, tid); CP_COMMIT();

    int bc = 0, bl = 2;
#pragma unroll 1
    for (int s = 0; s < S; s++) {
        CP_WAIT1();
        __syncthreads();
        if (s + 2 < S)
            dn_load(e, mbase, nbase, (s + 2) * 64, sbase + bl * DN_STAGE, tid);
        CP_COMMIT();

        uint32_t st = sbase + bc * DN_STAGE;
#pragma unroll
        for (int ks = 0; ks < 4; ks++) {
            uint32_t a[2][4];
#pragma unroll
            for (int mt = 0; mt < 2; mt++) {
                uint32_t aa = st + (wm + mt * 16 + (lane & 15)) * 144
                            + (ks * 16 + (lane >> 4) * 8) * 2;
                LDSM4(a[mt], aa);
            }
#pragma unroll
            for (int ng = 0; ng < 4; ng++) {
                uint32_t ba = st + 18432 + (ks * 16 + (lane & 15)) * 272
                            + (wn + ng * 16 + (lane >> 4) * 8) * 2;
                uint32_t bh[4];
                LDSM4T(bh, ba);
#pragma unroll
                for (int half = 0; half < 2; half++) {
                    int j = ng * 2 + half;
#pragma unroll
                    for (int mt = 0; mt < 2; mt++)
                        MMA_F16(acc[mt][j], a[mt], &bh[half * 2]);
                }
            }
        }
        bc = (bc == 2) ? 0 : bc + 1;
        bl = (bl == 2) ? 0 : bl + 1;
    }

#pragma unroll
    for (int mt = 0; mt < 2; mt++) {
#pragma unroll
        for (int rh = 0; rh < 2; rh++) {
            int m = wm + mt * 16 + (lane >> 2) + rh * 8;
            int tok = stok[m];
            if (tok < 0) continue;
            float* op = &out[(size_t)tok * HID + nbase];
#pragma unroll
            for (int j = 0; j < 8; j++) {
                int col = wn + (j >> 1) * 16 + (j & 1) * 8 + (lane & 3) * 2;
                atomicAdd(op + col,     acc[mt][j][rh * 2 + 0]);
                atomicAdd(op + col + 1, acc[mt][j][rh * 2 + 1]);
            }
        }
    }
}

// ---------------- launch (round-15 structure) ----------------
extern "C" void kernel_launch(void* const* d_in, const int* in_sizes, int n_in,
                              void* d_out, int out_size)
{
    const float* x    = (const float*)d_in[0];
    const float* rw   = (const float*)d_in[1];
    const float* gup  = (const float*)d_in[2];
    const float* dw   = (const float*)d_in[3];
    float* out = (float*)d_out;

    static cudaStream_t s2 = nullptr;
    static cudaEvent_t  ev_fork = nullptr, ev_gup = nullptr, ev_dw = nullptr;
    static bool init_done = false;
    if (!init_done) {
        cudaFuncSetAttribute(gateup_mma, cudaFuncAttributeMaxDynamicSharedMemorySize, GU_SMEM);
        cudaFuncSetAttribute(down_mma,   cudaFuncAttributeMaxDynamicSharedMemorySize, DN_SMEM);
        cudaStreamCreateWithFlags(&s2, cudaStreamNonBlocking);
        cudaEventCreateWithFlags(&ev_fork, cudaEventDisableTiming);
        cudaEventCreateWithFlags(&ev_gup,  cudaEventDisableTiming);
        cudaEventCreateWithFlags(&ev_dw,   cudaEventDisableTiming);
        init_done = true;
    }

    __half *xh, *gh, *dh;
    cudaGetSymbolAddress((void**)&xh, g_xh);
    cudaGetSymbolAddress((void**)&gh, g_gh);
    cudaGetSymbolAddress((void**)&dh, g_dh);

    cudaStream_t s1 = 0;

    // fork side stream
    cudaEventRecord(ev_fork, s1);
    cudaStreamWaitEvent(s2, ev_fork, 0);

    // s2: weight conversions (gup first — it gates gateup)
    int n4g = NEXP * HID * INTER2 / 4;
    convh_kernel<<<(n4g / 2 + 255) / 256, 256, 0, s2>>>(
        (const float4*)gup, (uint2*)gh, n4g);
    cudaEventRecord(ev_gup, s2);
    int n4d = NEXP * INTER * HID / 4;
    convh_kernel<<<(n4d / 2 + 255) / 256, 256, 0, s2>>>(
        (const float4*)dw, (uint2*)dh, n4d);
    cudaEventRecord(ev_dw, s2);

    // s1: zero + router (router also produces fp16 x)
    int n_out = T_TOK * HID;
    zero_kernel<<<(n_out + 511) / 512, 512, 0, s1>>>(out, n_out);
    router_kernel<<<T_TOK / 4, 128, 0, s1>>>(x, rw, xh);

    // gateup needs gup fp16
    cudaStreamWaitEvent(s1, ev_gup, 0);
    dim3 gridG(T_TOK / 64, INTER / 64, NEXP);    // (16, 12, 16)
    gateup_mma<<<gridG, 256, GU_SMEM, s1>>>(0);

    // down needs dw fp16 (converted concurrently with gateup)
    cudaStreamWaitEvent(s1, ev_dw, 0);
    dim3 gridD(T_TOK / 128, HID / 128, NEXP);    // (8, 16, 16)
    down_mma<<<gridD, 256, DN_SMEM, s1>>>(out);
}